// round 1
// baseline (speedup 1.0000x reference)
#include <cuda_runtime.h>
#include <math.h>

#define N_OBJ  100000
#define N_EVT  200000
#define N_EDGE 1000000
#define D      128

// ---------------- scratch (device globals; no allocation) ----------------
__device__ float g_hproj[(size_t)N_OBJ * D];      // object_X @ Wa^T + ba
__device__ float g_csum [(size_t)N_EVT * D];      // scatter-sum into events
__device__ float g_cnt  [N_EVT];                  // edge counts per event
__device__ float g_ctx  [(size_t)N_EVT * 2 * D];  // concat(event_X, c_atm)
__device__ float g_h1   [(size_t)N_EVT * D];      // relu(ctx@W1^T+b1)
__device__ float g_teff [(size_t)N_OBJ * D];      // scatter-add into objects
__device__ float g_gi   [(size_t)N_OBJ * 3 * D];  // x @ Wih^T + bih
__device__ float g_gh   [(size_t)N_OBJ * 3 * D];  // h @ Whh^T + bhh

// ---------------- helpers ----------------
__device__ __forceinline__ void red4(float* addr, float4 v) {
    asm volatile("red.global.add.v4.f32 [%0], {%1, %2, %3, %4};"
                 :: "l"(addr), "f"(v.x), "f"(v.y), "f"(v.z), "f"(v.w)
                 : "memory");
}

__device__ __forceinline__ float sigmoidf_(float x) {
    return 1.0f / (1.0f + expf(-x));
}

// ---------------- zero scratch ----------------
__global__ void zero_scratch() {
    int i = blockIdx.x * blockDim.x + threadIdx.x;
    const int n1 = N_EVT * D / 4;   // csum float4s
    const int n2 = N_EVT / 4;       // cnt float4s
    const int n3 = N_OBJ * D / 4;   // teff float4s
    float4 z = make_float4(0.f, 0.f, 0.f, 0.f);
    if (i < n1) reinterpret_cast<float4*>(g_csum)[i] = z;
    if (i < n2) reinterpret_cast<float4*>(g_cnt)[i]  = z;
    if (i < n3) reinterpret_cast<float4*>(g_teff)[i] = z;
}

// ---------------- tiled SGEMM: C[M,N] = act(A[M,K] @ W[N,K]^T + bias) ------
// BM=64, BN=64, BK=16, 128 threads, each thread computes 8x4 outputs.
template<int RELU>
__global__ __launch_bounds__(128)
void gemm_bias(const float* __restrict__ A, const float* __restrict__ W,
               const float* __restrict__ bias, float* __restrict__ C,
               int M, int N, int K) {
    constexpr int BM = 64, BN = 64, BK = 16, TM = 8, TN = 4;
    __shared__ float As[BK][BM + 1];
    __shared__ float Bs[BK][BN + 1];
    const int bm = blockIdx.y * BM;
    const int bn = blockIdx.x * BN;
    const int tid = threadIdx.x;
    const int tx = tid % (BN / TN);   // 0..15
    const int ty = tid / (BN / TN);   // 0..7

    float acc[TM][TN];
    #pragma unroll
    for (int i = 0; i < TM; i++)
        #pragma unroll
        for (int j = 0; j < TN; j++) acc[i][j] = 0.f;

    for (int k0 = 0; k0 < K; k0 += BK) {
        // load A tile (transposed into smem): BM*BK = 1024 floats
        #pragma unroll
        for (int it = 0; it < 2; it++) {
            int idx = (tid + it * 128) * 4;
            int m = idx / BK, kk = idx % BK;
            float4 v = make_float4(0.f, 0.f, 0.f, 0.f);
            if (bm + m < M)
                v = *reinterpret_cast<const float4*>(&A[(size_t)(bm + m) * K + k0 + kk]);
            As[kk + 0][m] = v.x; As[kk + 1][m] = v.y;
            As[kk + 2][m] = v.z; As[kk + 3][m] = v.w;
        }
        // load W tile (N is always a multiple of 64 here -> no guard)
        #pragma unroll
        for (int it = 0; it < 2; it++) {
            int idx = (tid + it * 128) * 4;
            int n = idx / BK, kk = idx % BK;
            float4 v = *reinterpret_cast<const float4*>(&W[(size_t)(bn + n) * K + k0 + kk]);
            Bs[kk + 0][n] = v.x; Bs[kk + 1][n] = v.y;
            Bs[kk + 2][n] = v.z; Bs[kk + 3][n] = v.w;
        }
        __syncthreads();

        #pragma unroll
        for (int kk = 0; kk < BK; kk++) {
            float a[TM], b[TN];
            #pragma unroll
            for (int i = 0; i < TM; i++) a[i] = As[kk][ty * TM + i];
            #pragma unroll
            for (int j = 0; j < TN; j++) b[j] = Bs[kk][tx * TN + j];
            #pragma unroll
            for (int i = 0; i < TM; i++)
                #pragma unroll
                for (int j = 0; j < TN; j++)
                    acc[i][j] = fmaf(a[i], b[j], acc[i][j]);
        }
        __syncthreads();
    }

    #pragma unroll
    for (int i = 0; i < TM; i++) {
        int m = bm + ty * TM + i;
        if (m >= M) continue;
        #pragma unroll
        for (int j = 0; j < TN; j++) {
            int n = bn + tx * TN + j;
            float v = acc[i][j] + bias[n];
            if (RELU) v = fmaxf(v, 0.f);
            C[(size_t)m * N + n] = v;
        }
    }
}

// ---------------- edge scatter: h_proj[obj] -> sum into events -----------
__global__ void scatter_obj_to_evt(const int* __restrict__ obj_idx,
                                   const int* __restrict__ evt_idx) {
    int gid = blockIdx.x * blockDim.x + threadIdx.x;   // N_EDGE * 32 threads
    if (gid >= N_EDGE * 32) return;
    int e = gid >> 5;
    int c = gid & 31;
    int o  = __ldg(obj_idx + e);
    int ev = __ldg(evt_idx + e);
    float4 v = *reinterpret_cast<const float4*>(&g_hproj[(size_t)o * D + c * 4]);
    red4(&g_csum[(size_t)ev * D + c * 4], v);
    if (c == 0) atomicAdd(&g_cnt[ev], 1.0f);
}

// ---------------- build ctx = [event_X | c_sum/max(cnt,1)] --------------
__global__ void build_ctx(const float* __restrict__ evX) {
    int gid = blockIdx.x * blockDim.x + threadIdx.x;   // N_EVT * 64 threads
    if (gid >= N_EVT * 64) return;
    int r = gid >> 6;
    int c4 = gid & 63;
    float4 v;
    if (c4 < 32) {
        v = *reinterpret_cast<const float4*>(&evX[(size_t)r * D + c4 * 4]);
    } else {
        float inv = 1.0f / fmaxf(__ldg(&g_cnt[r]), 1.0f);
        float4 s = *reinterpret_cast<const float4*>(&g_csum[(size_t)r * D + (c4 - 32) * 4]);
        v = make_float4(s.x * inv, s.y * inv, s.z * inv, s.w * inv);
    }
    *reinterpret_cast<float4*>(&g_ctx[(size_t)r * 2 * D + c4 * 4]) = v;
}

// ---------------- edge scatter: h_impulse[evt] -> sum into objects -------
__global__ void scatter_evt_to_obj(const int* __restrict__ obj_idx,
                                   const int* __restrict__ evt_idx,
                                   const float* __restrict__ himp) {
    int gid = blockIdx.x * blockDim.x + threadIdx.x;   // N_EDGE * 32 threads
    if (gid >= N_EDGE * 32) return;
    int e = gid >> 5;
    int c = gid & 31;
    int o  = __ldg(obj_idx + e);
    int ev = __ldg(evt_idx + e);
    float4 v = *reinterpret_cast<const float4*>(&himp[(size_t)ev * D + c * 4]);
    red4(&g_teff[(size_t)o * D + c * 4], v);
}

// ---------------- GRU gate math -----------------------------------------
__global__ void gru_gates(const float* __restrict__ objX, float* __restrict__ out) {
    int gid = blockIdx.x * blockDim.x + threadIdx.x;   // N_OBJ * 128 threads
    if (gid >= N_OBJ * D) return;
    int r = gid >> 7;
    int d = gid & 127;
    size_t base = (size_t)r * 3 * D + d;
    float ir = g_gi[base], iz = g_gi[base + D], in_ = g_gi[base + 2 * D];
    float hr = g_gh[base], hz = g_gh[base + D], hn  = g_gh[base + 2 * D];
    float h = objX[(size_t)r * D + d];
    float rg = sigmoidf_(ir + hr);
    float z  = sigmoidf_(iz + hz);
    float n  = tanhf(in_ + rg * hn);
    out[(size_t)r * D + d] = (1.0f - z) * n + z * h;
}

// ---------------- launch ------------------------------------------------
extern "C" void kernel_launch(void* const* d_in, const int* in_sizes, int n_in,
                              void* d_out, int out_size) {
    const float* event_X  = (const float*)d_in[0];
    const float* object_X = (const float*)d_in[1];
    const int*   evt_idx  = (const int*)d_in[2];
    const int*   obj_idx  = (const int*)d_in[3];
    const float* Wa  = (const float*)d_in[4];
    const float* ba  = (const float*)d_in[5];
    const float* W1  = (const float*)d_in[6];
    const float* b1  = (const float*)d_in[7];
    const float* W2  = (const float*)d_in[8];
    const float* b2  = (const float*)d_in[9];
    const float* Wih = (const float*)d_in[10];
    const float* Whh = (const float*)d_in[11];
    const float* bih = (const float*)d_in[12];
    const float* bhh = (const float*)d_in[13];

    float* out = (float*)d_out;
    float* out_newobj = out;                       // [N_OBJ, 128]
    float* out_himp   = out + (size_t)N_OBJ * D;   // [N_EVT, 128]

    float* hproj = nullptr; cudaGetSymbolAddress((void**)&hproj, g_hproj);
    float* ctx   = nullptr; cudaGetSymbolAddress((void**)&ctx,   g_ctx);
    float* h1    = nullptr; cudaGetSymbolAddress((void**)&h1,    g_h1);
    float* teff  = nullptr; cudaGetSymbolAddress((void**)&teff,  g_teff);
    float* gi    = nullptr; cudaGetSymbolAddress((void**)&gi,    g_gi);
    float* gh    = nullptr; cudaGetSymbolAddress((void**)&gh,    g_gh);

    // 1. zero accumulators
    {
        int n = N_EVT * D / 4;
        zero_scratch<<<(n + 255) / 256, 256>>>();
    }

    // 2. h_obj_proj = object_X @ Wa^T + ba   [N_OBJ, 128]
    gemm_bias<0><<<dim3(D / 64, (N_OBJ + 63) / 64), 128>>>(
        object_X, Wa, ba, hproj, N_OBJ, D, D);

    // 3. scatter-sum object projections into events + counts
    scatter_obj_to_evt<<<(N_EDGE * 32 + 255) / 256, 256>>>(obj_idx, evt_idx);

    // 4. ctx = [event_X | mean]   [N_EVT, 256]
    build_ctx<<<(N_EVT * 64 + 255) / 256, 256>>>(event_X);

    // 5. h1 = relu(ctx @ W1^T + b1)   [N_EVT, 128]
    gemm_bias<1><<<dim3(D / 64, (N_EVT + 63) / 64), 128>>>(
        ctx, W1, b1, h1, N_EVT, D, 2 * D);

    // 6. h_impulse = h1 @ W2^T + b2 -> directly into output
    gemm_bias<0><<<dim3(D / 64, (N_EVT + 63) / 64), 128>>>(
        h1, W2, b2, out_himp, N_EVT, D, D);

    // 7. scatter-add impulses into objects
    scatter_evt_to_obj<<<(N_EDGE * 32 + 255) / 256, 256>>>(obj_idx, evt_idx, out_himp);

    // 8. gi = total_effect @ Wih^T + bih   [N_OBJ, 384]
    gemm_bias<0><<<dim3(3 * D / 64, (N_OBJ + 63) / 64), 128>>>(
        teff, Wih, bih, gi, N_OBJ, 3 * D, D);

    // 9. gh = object_X @ Whh^T + bhh   [N_OBJ, 384]
    gemm_bias<0><<<dim3(3 * D / 64, (N_OBJ + 63) / 64), 128>>>(
        object_X, Whh, bhh, gh, N_OBJ, 3 * D, D);

    // 10. GRU gate math -> new_object_X
    gru_gates<<<(N_OBJ * D + 255) / 256, 256>>>(object_X, out_newobj);
}

// round 3
// speedup vs baseline: 1.7536x; 1.7536x over previous
#include <cuda_runtime.h>
#include <math.h>
#include <stdint.h>

#define N_OBJ  100000
#define N_EVT  200000
#define N_EDGE 1000000
#define D      128

// ---------------- scratch (device globals; no allocation) ----------------
__device__ float g_hproj[(size_t)N_OBJ * D];      // object_X @ Wa^T + ba
__device__ float g_csum [(size_t)N_EVT * D];      // scatter-sum into events
__device__ float g_cnt  [N_EVT];                  // edge counts per event
__device__ float g_ctx  [(size_t)N_EVT * 2 * D];  // concat(event_X, c_atm)
__device__ float g_h1   [(size_t)N_EVT * D];      // relu(ctx@W1^T+b1)
__device__ float g_teff [(size_t)N_OBJ * D];      // scatter-add into objects
__device__ float g_gi   [(size_t)N_OBJ * 3 * D];  // x @ Wih^T + bih
__device__ float g_gh   [(size_t)N_OBJ * 3 * D];  // h @ Whh^T + bhh

// ---------------- helpers ----------------
__device__ __forceinline__ uint32_t tf32r(float f) {
    uint32_t o;
    asm("cvt.rna.tf32.f32 %0, %1;" : "=r"(o) : "f"(f));
    return o;
}

__device__ __forceinline__ void red4(float* addr, float4 v) {
    asm volatile("red.global.add.v4.f32 [%0], {%1, %2, %3, %4};"
                 :: "l"(addr), "f"(v.x), "f"(v.y), "f"(v.z), "f"(v.w)
                 : "memory");
}

__device__ __forceinline__ float sigmoidf_(float x) {
    return 1.0f / (1.0f + expf(-x));
}

__device__ __forceinline__ void mma_tf32(float* c, const uint32_t* a,
                                         const uint32_t* b) {
    asm volatile(
        "mma.sync.aligned.m16n8k8.row.col.f32.tf32.tf32.f32 "
        "{%0,%1,%2,%3}, {%4,%5,%6,%7}, {%8,%9}, {%0,%1,%2,%3};"
        : "+f"(c[0]), "+f"(c[1]), "+f"(c[2]), "+f"(c[3])
        : "r"(a[0]), "r"(a[1]), "r"(a[2]), "r"(a[3]), "r"(b[0]), "r"(b[1]));
}

// ---------------- zero scratch ----------------
__global__ void zero_scratch() {
    int i = blockIdx.x * blockDim.x + threadIdx.x;
    const int n1 = N_EVT * D / 4;   // csum float4s
    const int n2 = N_EVT / 4;       // cnt float4s
    const int n3 = N_OBJ * D / 4;   // teff float4s
    float4 z = make_float4(0.f, 0.f, 0.f, 0.f);
    if (i < n1) reinterpret_cast<float4*>(g_csum)[i] = z;
    if (i < n2) reinterpret_cast<float4*>(g_cnt)[i]  = z;
    if (i < n3) reinterpret_cast<float4*>(g_teff)[i] = z;
}

// =====================================================================
// Warp-level tf32 mma.sync GEMM: C[M,N] = act(A[M,K] @ W[N,K]^T + bias)
// CTA tile 128x128, BK=16, 256 threads = 8 warps (2m x 4n),
// warp tile 64x32 (4 m-tiles x 4 n-tiles of m16n8k8). Double-buffered SMEM.
// SMEM layout [row][BK+4] (stride 20 words) -> conflict-free fragment LDS.
// =====================================================================
#define BK   16
#define LDSW 20   // BK + 4 pad

template<int RELU>
__global__ __launch_bounds__(256)
void gemm_mma(const float* __restrict__ A, const float* __restrict__ W,
              const float* __restrict__ bias, float* __restrict__ C,
              int M, int N, int K) {
    __shared__ uint32_t As[2][128 * LDSW];
    __shared__ uint32_t Bs[2][128 * LDSW];

    const int tid = threadIdx.x;
    const int wid = tid >> 5;
    const int lane = tid & 31;
    const int gq = lane >> 2;      // groupID 0..7
    const int tg = lane & 3;       // thread-in-group 0..3
    const int warp_m = wid >> 2;   // 0..1  -> 64 rows
    const int warp_n = wid & 3;    // 0..3  -> 32 cols
    const int bm = blockIdx.y * 128;
    const int bn = blockIdx.x * 128;

    // global-load coordinates: 512 float4 per tile, 2 per thread
    const int r0 = tid >> 2;             // rows tid/4 and tid/4+64
    const int c4 = (tid & 3) * 4;        // k offset (floats)

    float acc[4][4][4];
    #pragma unroll
    for (int i = 0; i < 4; i++)
        #pragma unroll
        for (int j = 0; j < 4; j++)
            #pragma unroll
            for (int q = 0; q < 4; q++) acc[i][j][q] = 0.f;

    const int CHUNKS = K >> 4;

    float4 stA[2], stB[2];
    auto ldg_chunk = [&](int c) {
        const int k0 = c * BK + c4;
        #pragma unroll
        for (int h = 0; h < 2; h++) {
            int r = r0 + h * 64;
            stA[h] = make_float4(0.f, 0.f, 0.f, 0.f);
            if (bm + r < M)
                stA[h] = *reinterpret_cast<const float4*>(&A[(size_t)(bm + r) * K + k0]);
            stB[h] = *reinterpret_cast<const float4*>(&W[(size_t)(bn + r) * K + k0]);
        }
    };
    auto sts_chunk = [&](int p) {
        #pragma unroll
        for (int h = 0; h < 2; h++) {
            int r = r0 + h * 64;
            uint32_t* a = &As[p][r * LDSW + c4];
            a[0] = tf32r(stA[h].x); a[1] = tf32r(stA[h].y);
            a[2] = tf32r(stA[h].z); a[3] = tf32r(stA[h].w);
            uint32_t* b = &Bs[p][r * LDSW + c4];
            b[0] = tf32r(stB[h].x); b[1] = tf32r(stB[h].y);
            b[2] = tf32r(stB[h].z); b[3] = tf32r(stB[h].w);
        }
    };

    ldg_chunk(0);
    sts_chunk(0);
    __syncthreads();

    for (int c = 0; c < CHUNKS; c++) {
        const int p = c & 1;
        if (c + 1 < CHUNKS) ldg_chunk(c + 1);

        #pragma unroll
        for (int ks = 0; ks < 2; ks++) {
            const int kb = ks * 8;
            uint32_t af[4][4], bf[4][2];
            #pragma unroll
            for (int mt = 0; mt < 4; mt++) {
                int row = warp_m * 64 + mt * 16 + gq;
                af[mt][0] = As[p][(row    ) * LDSW + kb + tg];
                af[mt][1] = As[p][(row + 8) * LDSW + kb + tg];
                af[mt][2] = As[p][(row    ) * LDSW + kb + tg + 4];
                af[mt][3] = As[p][(row + 8) * LDSW + kb + tg + 4];
            }
            #pragma unroll
            for (int nt = 0; nt < 4; nt++) {
                int n = warp_n * 32 + nt * 8 + gq;
                bf[nt][0] = Bs[p][n * LDSW + kb + tg];
                bf[nt][1] = Bs[p][n * LDSW + kb + tg + 4];
            }
            #pragma unroll
            for (int mt = 0; mt < 4; mt++)
                #pragma unroll
                for (int nt = 0; nt < 4; nt++)
                    mma_tf32(acc[mt][nt], af[mt], bf[nt]);
        }

        if (c + 1 < CHUNKS) {
            __syncthreads();
            sts_chunk(p ^ 1);
            __syncthreads();
        }
    }

    // epilogue
    #pragma unroll
    for (int mt = 0; mt < 4; mt++) {
        #pragma unroll
        for (int half = 0; half < 2; half++) {
            int m = bm + warp_m * 64 + mt * 16 + gq + half * 8;
            if (m >= M) continue;
            #pragma unroll
            for (int nt = 0; nt < 4; nt++) {
                int n = bn + warp_n * 32 + nt * 8 + tg * 2;
                float2 bb = *reinterpret_cast<const float2*>(&bias[n]);
                float2 o;
                o.x = acc[mt][nt][half * 2 + 0] + bb.x;
                o.y = acc[mt][nt][half * 2 + 1] + bb.y;
                if (RELU) { o.x = fmaxf(o.x, 0.f); o.y = fmaxf(o.y, 0.f); }
                *reinterpret_cast<float2*>(&C[(size_t)m * N + n]) = o;
            }
        }
    }
}

// ---------------- edge scatter: h_proj[obj] -> sum into events -----------
__global__ void scatter_obj_to_evt(const int* __restrict__ obj_idx,
                                   const int* __restrict__ evt_idx) {
    int gid = blockIdx.x * blockDim.x + threadIdx.x;
    if (gid >= N_EDGE * 32) return;
    int e = gid >> 5;
    int c = gid & 31;
    int o  = __ldg(obj_idx + e);
    int ev = __ldg(evt_idx + e);
    float4 v = *reinterpret_cast<const float4*>(&g_hproj[(size_t)o * D + c * 4]);
    red4(&g_csum[(size_t)ev * D + c * 4], v);
    if (c == 0) atomicAdd(&g_cnt[ev], 1.0f);
}

// ---------------- build ctx = [event_X | c_sum/max(cnt,1)] --------------
__global__ void build_ctx(const float* __restrict__ evX) {
    int gid = blockIdx.x * blockDim.x + threadIdx.x;
    if (gid >= N_EVT * 64) return;
    int r = gid >> 6;
    int c4 = gid & 63;
    float4 v;
    if (c4 < 32) {
        v = *reinterpret_cast<const float4*>(&evX[(size_t)r * D + c4 * 4]);
    } else {
        float inv = 1.0f / fmaxf(__ldg(&g_cnt[r]), 1.0f);
        float4 s = *reinterpret_cast<const float4*>(&g_csum[(size_t)r * D + (c4 - 32) * 4]);
        v = make_float4(s.x * inv, s.y * inv, s.z * inv, s.w * inv);
    }
    *reinterpret_cast<float4*>(&g_ctx[(size_t)r * 2 * D + c4 * 4]) = v;
}

// ---------------- edge scatter: h_impulse[evt] -> sum into objects -------
__global__ void scatter_evt_to_obj(const int* __restrict__ obj_idx,
                                   const int* __restrict__ evt_idx,
                                   const float* __restrict__ himp) {
    int gid = blockIdx.x * blockDim.x + threadIdx.x;
    if (gid >= N_EDGE * 32) return;
    int e = gid >> 5;
    int c = gid & 31;
    int o  = __ldg(obj_idx + e);
    int ev = __ldg(evt_idx + e);
    float4 v = *reinterpret_cast<const float4*>(&himp[(size_t)ev * D + c * 4]);
    red4(&g_teff[(size_t)o * D + c * 4], v);
}

// ---------------- GRU gate math -----------------------------------------
__global__ void gru_gates(const float* __restrict__ objX, float* __restrict__ out) {
    int gid = blockIdx.x * blockDim.x + threadIdx.x;
    if (gid >= N_OBJ * D) return;
    int r = gid >> 7;
    int d = gid & 127;
    size_t base = (size_t)r * 3 * D + d;
    float ir = g_gi[base], iz = g_gi[base + D], in_ = g_gi[base + 2 * D];
    float hr = g_gh[base], hz = g_gh[base + D], hn  = g_gh[base + 2 * D];
    float h = objX[(size_t)r * D + d];
    float rg = sigmoidf_(ir + hr);
    float z  = sigmoidf_(iz + hz);
    float n  = tanhf(in_ + rg * hn);
    out[(size_t)r * D + d] = (1.0f - z) * n + z * h;
}

// ---------------- launch ------------------------------------------------
extern "C" void kernel_launch(void* const* d_in, const int* in_sizes, int n_in,
                              void* d_out, int out_size) {
    const float* event_X  = (const float*)d_in[0];
    const float* object_X = (const float*)d_in[1];
    const int*   evt_idx  = (const int*)d_in[2];
    const int*   obj_idx  = (const int*)d_in[3];
    const float* Wa  = (const float*)d_in[4];
    const float* ba  = (const float*)d_in[5];
    const float* W1  = (const float*)d_in[6];
    const float* b1  = (const float*)d_in[7];
    const float* W2  = (const float*)d_in[8];
    const float* b2  = (const float*)d_in[9];
    const float* Wih = (const float*)d_in[10];
    const float* Whh = (const float*)d_in[11];
    const float* bih = (const float*)d_in[12];
    const float* bhh = (const float*)d_in[13];

    float* out = (float*)d_out;
    float* out_newobj = out;                       // [N_OBJ, 128]
    float* out_himp   = out + (size_t)N_OBJ * D;   // [N_EVT, 128]

    float* hproj = nullptr; cudaGetSymbolAddress((void**)&hproj, g_hproj);
    float* ctx   = nullptr; cudaGetSymbolAddress((void**)&ctx,   g_ctx);
    float* h1    = nullptr; cudaGetSymbolAddress((void**)&h1,    g_h1);
    float* teff  = nullptr; cudaGetSymbolAddress((void**)&teff,  g_teff);
    float* gi    = nullptr; cudaGetSymbolAddress((void**)&gi,    g_gi);
    float* gh    = nullptr; cudaGetSymbolAddress((void**)&gh,    g_gh);

    // 1. zero accumulators
    {
        int n = N_EVT * D / 4;
        zero_scratch<<<(n + 255) / 256, 256>>>();
    }

    // 2. h_obj_proj = object_X @ Wa^T + ba   [N_OBJ, 128]
    gemm_mma<0><<<dim3(1, (N_OBJ + 127) / 128), 256>>>(
        object_X, Wa, ba, hproj, N_OBJ, D, D);

    // 3. scatter-sum object projections into events + counts
    scatter_obj_to_evt<<<(N_EDGE * 32 + 255) / 256, 256>>>(obj_idx, evt_idx);

    // 4. ctx = [event_X | mean]   [N_EVT, 256]
    build_ctx<<<(N_EVT * 64 + 255) / 256, 256>>>(event_X);

    // 5. h1 = relu(ctx @ W1^T + b1)   [N_EVT, 128]
    gemm_mma<1><<<dim3(1, (N_EVT + 127) / 128), 256>>>(
        ctx, W1, b1, h1, N_EVT, D, 2 * D);

    // 6. h_impulse = h1 @ W2^T + b2 -> directly into output
    gemm_mma<0><<<dim3(1, (N_EVT + 127) / 128), 256>>>(
        h1, W2, b2, out_himp, N_EVT, D, D);

    // 7. scatter-add impulses into objects
    scatter_evt_to_obj<<<(N_EDGE * 32 + 255) / 256, 256>>>(obj_idx, evt_idx, out_himp);

    // 8. gi = total_effect @ Wih^T + bih   [N_OBJ, 384]
    gemm_mma<0><<<dim3(3, (N_OBJ + 127) / 128), 256>>>(
        teff, Wih, bih, gi, N_OBJ, 3 * D, D);

    // 9. gh = object_X @ Whh^T + bhh   [N_OBJ, 384]
    gemm_mma<0><<<dim3(3, (N_OBJ + 127) / 128), 256>>>(
        object_X, Whh, bhh, gh, N_OBJ, 3 * D, D);

    // 10. GRU gate math -> new_object_X
    gru_gates<<<(N_OBJ * D + 255) / 256, 256>>>(object_X, out_newobj);
}

// round 4
// speedup vs baseline: 1.7984x; 1.0255x over previous
#include <cuda_runtime.h>
#include <math.h>
#include <stdint.h>

#define N_OBJ  100000
#define N_EVT  200000
#define N_EDGE 1000000
#define D      128

// ---------------- scratch (device globals; no allocation) ----------------
__device__ float g_hproj[(size_t)N_OBJ * D];      // object_X @ Wa^T + ba
__device__ float g_csum [(size_t)N_EVT * D];      // scatter-sum into events
__device__ float g_cnt  [N_EVT];                  // edge counts per event
__device__ float g_h1   [(size_t)N_EVT * D];      // relu(ctx@W1^T+b1)
__device__ float g_teff [(size_t)N_OBJ * D];      // scatter-add into objects
__device__ float g_gi   [(size_t)N_OBJ * 3 * D];  // x @ Wih^T + bih
__device__ float g_gh   [(size_t)N_OBJ * 3 * D];  // h @ Whh^T + bhh

// ---------------- helpers ----------------
__device__ __forceinline__ uint32_t tf32r(float f) {
    uint32_t o;
    asm("cvt.rna.tf32.f32 %0, %1;" : "=r"(o) : "f"(f));
    return o;
}

__device__ __forceinline__ void red4(float* addr, float4 v) {
    asm volatile("red.global.add.v4.f32 [%0], {%1, %2, %3, %4};"
                 :: "l"(addr), "f"(v.x), "f"(v.y), "f"(v.z), "f"(v.w)
                 : "memory");
}

__device__ __forceinline__ float sigmoidf_(float x) {
    return 1.0f / (1.0f + expf(-x));
}

__device__ __forceinline__ void mma_tf32(float* c, const uint32_t* a,
                                         const uint32_t* b) {
    asm volatile(
        "mma.sync.aligned.m16n8k8.row.col.f32.tf32.tf32.f32 "
        "{%0,%1,%2,%3}, {%4,%5,%6,%7}, {%8,%9}, {%0,%1,%2,%3};"
        : "+f"(c[0]), "+f"(c[1]), "+f"(c[2]), "+f"(c[3])
        : "r"(a[0]), "r"(a[1]), "r"(a[2]), "r"(a[3]), "r"(b[0]), "r"(b[1]));
}

// ---------------- zero scratch ----------------
__global__ void zero_scratch() {
    int i = blockIdx.x * blockDim.x + threadIdx.x;
    const int n1 = N_EVT * D / 4;   // csum float4s
    const int n2 = N_EVT / 4;       // cnt float4s
    const int n3 = N_OBJ * D / 4;   // teff float4s
    float4 z = make_float4(0.f, 0.f, 0.f, 0.f);
    if (i < n1) reinterpret_cast<float4*>(g_csum)[i] = z;
    if (i < n2) reinterpret_cast<float4*>(g_cnt)[i]  = z;
    if (i < n3) reinterpret_cast<float4*>(g_teff)[i] = z;
}

// =====================================================================
// Warp-level tf32 mma.sync GEMM: C[M,N] = act(A[M,K] @ W[N,K]^T + bias)
// CTA tile 128x128, BK=16, 128 threads = 4 warps (2m x 2n),
// warp tile 64x64 (4 m-tiles x 8 n-tiles of m16n8k8). Double-buffered SMEM.
// SMEM layout [row][BK+4] (stride 20 words) -> conflict-free fragment LDS.
// CTX=1: A is the virtual concat [event_X | csum/max(cnt,1)], K=256.
// =====================================================================
#define BK   16
#define LDSW 20   // BK + 4 pad

template<int RELU, int CTX>
__global__ __launch_bounds__(128, 2)
void gemm_mma(const float* __restrict__ A, const float* __restrict__ A2,
              const float* __restrict__ cntp,
              const float* __restrict__ W,
              const float* __restrict__ bias, float* __restrict__ C,
              int M, int N, int K) {
    __shared__ uint32_t As[2][128 * LDSW];
    __shared__ uint32_t Bs[2][128 * LDSW];

    const int tid = threadIdx.x;
    const int wid = tid >> 5;
    const int lane = tid & 31;
    const int gq = lane >> 2;      // groupID 0..7
    const int tg = lane & 3;       // thread-in-group 0..3
    const int warp_m = wid >> 1;   // 0..1  -> 64 rows
    const int warp_n = wid & 1;    // 0..1  -> 64 cols
    const int bm = blockIdx.y * 128;
    const int bn = blockIdx.x * 128;

    // global-load coordinates: 512 float4 per tile, 4 per thread
    const int r0 = tid >> 2;             // base row (0..31), rows r0+h*32
    const int c4 = (tid & 3) * 4;        // k offset (floats)

    float acc[4][8][4];
    #pragma unroll
    for (int i = 0; i < 4; i++)
        #pragma unroll
        for (int j = 0; j < 8; j++)
            #pragma unroll
            for (int q = 0; q < 4; q++) acc[i][j][q] = 0.f;

    const int CHUNKS = K >> 4;
    const int KA = CTX ? 128 : K;   // row stride (floats) of A / A2

    float4 stA[4], stB[4];
    auto ldg_chunk = [&](int c) {
        const int k0 = c * BK + c4;
        #pragma unroll
        for (int h = 0; h < 4; h++) {
            int r = r0 + h * 32;
            stA[h] = make_float4(0.f, 0.f, 0.f, 0.f);
            if (bm + r < M) {
                if (CTX) {
                    if (k0 < 128) {
                        stA[h] = *reinterpret_cast<const float4*>(
                            &A[(size_t)(bm + r) * KA + k0]);
                    } else {
                        float inv = 1.0f / fmaxf(__ldg(&cntp[bm + r]), 1.0f);
                        float4 s = *reinterpret_cast<const float4*>(
                            &A2[(size_t)(bm + r) * KA + (k0 - 128)]);
                        stA[h] = make_float4(s.x * inv, s.y * inv,
                                             s.z * inv, s.w * inv);
                    }
                } else {
                    stA[h] = *reinterpret_cast<const float4*>(
                        &A[(size_t)(bm + r) * KA + k0]);
                }
            }
            stB[h] = *reinterpret_cast<const float4*>(
                &W[(size_t)(bn + r) * K + k0]);
        }
    };
    auto sts_chunk = [&](int p) {
        #pragma unroll
        for (int h = 0; h < 4; h++) {
            int r = r0 + h * 32;
            uint32_t* a = &As[p][r * LDSW + c4];
            a[0] = tf32r(stA[h].x); a[1] = tf32r(stA[h].y);
            a[2] = tf32r(stA[h].z); a[3] = tf32r(stA[h].w);
            uint32_t* b = &Bs[p][r * LDSW + c4];
            b[0] = tf32r(stB[h].x); b[1] = tf32r(stB[h].y);
            b[2] = tf32r(stB[h].z); b[3] = tf32r(stB[h].w);
        }
    };

    ldg_chunk(0);
    sts_chunk(0);
    __syncthreads();

    for (int c = 0; c < CHUNKS; c++) {
        const int p = c & 1;
        if (c + 1 < CHUNKS) ldg_chunk(c + 1);

        #pragma unroll
        for (int ks = 0; ks < 2; ks++) {
            const int kb = ks * 8;
            uint32_t af[4][4], bf[8][2];
            #pragma unroll
            for (int mt = 0; mt < 4; mt++) {
                int row = warp_m * 64 + mt * 16 + gq;
                af[mt][0] = As[p][(row    ) * LDSW + kb + tg];
                af[mt][1] = As[p][(row + 8) * LDSW + kb + tg];
                af[mt][2] = As[p][(row    ) * LDSW + kb + tg + 4];
                af[mt][3] = As[p][(row + 8) * LDSW + kb + tg + 4];
            }
            #pragma unroll
            for (int nt = 0; nt < 8; nt++) {
                int n = warp_n * 64 + nt * 8 + gq;
                bf[nt][0] = Bs[p][n * LDSW + kb + tg];
                bf[nt][1] = Bs[p][n * LDSW + kb + tg + 4];
            }
            #pragma unroll
            for (int mt = 0; mt < 4; mt++)
                #pragma unroll
                for (int nt = 0; nt < 8; nt++)
                    mma_tf32(acc[mt][nt], af[mt], bf[nt]);
        }

        if (c + 1 < CHUNKS) {
            __syncthreads();
            sts_chunk(p ^ 1);
            __syncthreads();
        }
    }

    // epilogue
    #pragma unroll
    for (int mt = 0; mt < 4; mt++) {
        #pragma unroll
        for (int half = 0; half < 2; half++) {
            int m = bm + warp_m * 64 + mt * 16 + gq + half * 8;
            if (m >= M) continue;
            #pragma unroll
            for (int nt = 0; nt < 8; nt++) {
                int n = bn + warp_n * 64 + nt * 8 + tg * 2;
                float2 bb = *reinterpret_cast<const float2*>(&bias[n]);
                float2 o;
                o.x = acc[mt][nt][half * 2 + 0] + bb.x;
                o.y = acc[mt][nt][half * 2 + 1] + bb.y;
                if (RELU) { o.x = fmaxf(o.x, 0.f); o.y = fmaxf(o.y, 0.f); }
                *reinterpret_cast<float2*>(&C[(size_t)m * N + n]) = o;
            }
        }
    }
}

// ---------------- edge scatter: h_proj[obj] -> sum into events -----------
__global__ void scatter_obj_to_evt(const int* __restrict__ obj_idx,
                                   const int* __restrict__ evt_idx) {
    int gid = blockIdx.x * blockDim.x + threadIdx.x;
    if (gid >= N_EDGE * 32) return;
    int e = gid >> 5;
    int c = gid & 31;
    int o  = __ldg(obj_idx + e);
    int ev = __ldg(evt_idx + e);
    float4 v = *reinterpret_cast<const float4*>(&g_hproj[(size_t)o * D + c * 4]);
    red4(&g_csum[(size_t)ev * D + c * 4], v);
    if (c == 0) atomicAdd(&g_cnt[ev], 1.0f);
}

// ---------------- edge scatter: h_impulse[evt] -> sum into objects -------
__global__ void scatter_evt_to_obj(const int* __restrict__ obj_idx,
                                   const int* __restrict__ evt_idx,
                                   const float* __restrict__ himp) {
    int gid = blockIdx.x * blockDim.x + threadIdx.x;
    if (gid >= N_EDGE * 32) return;
    int e = gid >> 5;
    int c = gid & 31;
    int o  = __ldg(obj_idx + e);
    int ev = __ldg(evt_idx + e);
    float4 v = *reinterpret_cast<const float4*>(&himp[(size_t)ev * D + c * 4]);
    red4(&g_teff[(size_t)o * D + c * 4], v);
}

// ---------------- GRU gate math -----------------------------------------
__global__ void gru_gates(const float* __restrict__ objX, float* __restrict__ out) {
    int gid = blockIdx.x * blockDim.x + threadIdx.x;
    if (gid >= N_OBJ * D) return;
    int r = gid >> 7;
    int d = gid & 127;
    size_t base = (size_t)r * 3 * D + d;
    float ir = g_gi[base], iz = g_gi[base + D], in_ = g_gi[base + 2 * D];
    float hr = g_gh[base], hz = g_gh[base + D], hn  = g_gh[base + 2 * D];
    float h = objX[(size_t)r * D + d];
    float rg = sigmoidf_(ir + hr);
    float z  = sigmoidf_(iz + hz);
    float n  = tanhf(in_ + rg * hn);
    out[(size_t)r * D + d] = (1.0f - z) * n + z * h;
}

// ---------------- launch ------------------------------------------------
extern "C" void kernel_launch(void* const* d_in, const int* in_sizes, int n_in,
                              void* d_out, int out_size) {
    const float* event_X  = (const float*)d_in[0];
    const float* object_X = (const float*)d_in[1];
    const int*   evt_idx  = (const int*)d_in[2];
    const int*   obj_idx  = (const int*)d_in[3];
    const float* Wa  = (const float*)d_in[4];
    const float* ba  = (const float*)d_in[5];
    const float* W1  = (const float*)d_in[6];
    const float* b1  = (const float*)d_in[7];
    const float* W2  = (const float*)d_in[8];
    const float* b2  = (const float*)d_in[9];
    const float* Wih = (const float*)d_in[10];
    const float* Whh = (const float*)d_in[11];
    const float* bih = (const float*)d_in[12];
    const float* bhh = (const float*)d_in[13];

    float* out = (float*)d_out;
    float* out_newobj = out;                       // [N_OBJ, 128]
    float* out_himp   = out + (size_t)N_OBJ * D;   // [N_EVT, 128]

    float* hproj = nullptr; cudaGetSymbolAddress((void**)&hproj, g_hproj);
    float* csum  = nullptr; cudaGetSymbolAddress((void**)&csum,  g_csum);
    float* cnt   = nullptr; cudaGetSymbolAddress((void**)&cnt,   g_cnt);
    float* h1    = nullptr; cudaGetSymbolAddress((void**)&h1,    g_h1);
    float* teff  = nullptr; cudaGetSymbolAddress((void**)&teff,  g_teff);
    float* gi    = nullptr; cudaGetSymbolAddress((void**)&gi,    g_gi);
    float* gh    = nullptr; cudaGetSymbolAddress((void**)&gh,    g_gh);

    // 1. zero accumulators
    {
        int n = N_EVT * D / 4;
        zero_scratch<<<(n + 255) / 256, 256>>>();
    }

    // 2. h_obj_proj = object_X @ Wa^T + ba   [N_OBJ, 128]
    gemm_mma<0, 0><<<dim3(1, (N_OBJ + 127) / 128), 128>>>(
        object_X, nullptr, nullptr, Wa, ba, hproj, N_OBJ, D, D);

    // 3. scatter-sum object projections into events + counts
    scatter_obj_to_evt<<<(N_EDGE * 32 + 255) / 256, 256>>>(obj_idx, evt_idx);

    // 4+5. h1 = relu([event_X | csum/cnt] @ W1^T + b1)   (ctx fused in loader)
    gemm_mma<1, 1><<<dim3(1, (N_EVT + 127) / 128), 128>>>(
        event_X, csum, cnt, W1, b1, h1, N_EVT, D, 2 * D);

    // 6. h_impulse = h1 @ W2^T + b2 -> directly into output
    gemm_mma<0, 0><<<dim3(1, (N_EVT + 127) / 128), 128>>>(
        h1, nullptr, nullptr, W2, b2, out_himp, N_EVT, D, D);

    // 7. scatter-add impulses into objects
    scatter_evt_to_obj<<<(N_EDGE * 32 + 255) / 256, 256>>>(obj_idx, evt_idx, out_himp);

    // 8. gi = total_effect @ Wih^T + bih   [N_OBJ, 384]
    gemm_mma<0, 0><<<dim3(3, (N_OBJ + 127) / 128), 128>>>(
        teff, nullptr, nullptr, Wih, bih, gi, N_OBJ, 3 * D, D);

    // 9. gh = object_X @ Whh^T + bhh   [N_OBJ, 384]
    gemm_mma<0, 0><<<dim3(3, (N_OBJ + 127) / 128), 128>>>(
        object_X, nullptr, nullptr, Whh, bhh, gh, N_OBJ, 3 * D, D);

    // 10. GRU gate math -> new_object_X
    gru_gates<<<(N_OBJ * D + 255) / 256, 256>>>(object_X, out_newobj);
}

// round 5
// speedup vs baseline: 1.9882x; 1.1056x over previous
#include <cuda_runtime.h>
#include <math.h>
#include <stdint.h>

#define N_OBJ  100000
#define N_EVT  200000
#define N_EDGE 1000000
#define D      128

// ---------------- scratch (device globals; no allocation) ----------------
__device__ float g_hproj[(size_t)N_OBJ * D];      // object_X @ Wa^T + ba
__device__ float g_csum [(size_t)N_EVT * D];      // scatter-sum -> scaled mean
__device__ float g_cnt  [N_EVT];                  // edge counts per event
__device__ float g_h1   [(size_t)N_EVT * D];      // relu(ctx@W1^T+b1)
__device__ float g_teff [(size_t)N_OBJ * D];      // scatter-add into objects
__device__ float g_gi   [(size_t)N_OBJ * 3 * D];  // x @ Wih^T + bih
__device__ float g_gh   [(size_t)N_OBJ * 3 * D];  // h @ Whh^T + bhh

// ---------------- helpers ----------------
__device__ __forceinline__ uint32_t smem_u32(const void* p) {
    uint32_t a;
    asm("{ .reg .u64 t; cvta.to.shared.u64 t, %1; cvt.u32.u64 %0, t; }"
        : "=r"(a) : "l"(p));
    return a;
}

__device__ __forceinline__ uint32_t tf32r(float f) {
    uint32_t o;
    asm("cvt.rna.tf32.f32 %0, %1;" : "=r"(o) : "f"(f));
    return o;
}

__device__ __forceinline__ void cpasync16(uint32_t dst, const void* src, int sz) {
    asm volatile("cp.async.cg.shared.global [%0], [%1], 16, %2;"
                 :: "r"(dst), "l"(src), "r"(sz));
}

__device__ __forceinline__ void red4(float* addr, float4 v) {
    asm volatile("red.global.add.v4.f32 [%0], {%1, %2, %3, %4};"
                 :: "l"(addr), "f"(v.x), "f"(v.y), "f"(v.z), "f"(v.w)
                 : "memory");
}

__device__ __forceinline__ float sigmoidf_(float x) {
    return 1.0f / (1.0f + expf(-x));
}

__device__ __forceinline__ void mma_tf32(float* c, const uint32_t* a,
                                         const uint32_t* b) {
    asm volatile(
        "mma.sync.aligned.m16n8k8.row.col.f32.tf32.tf32.f32 "
        "{%0,%1,%2,%3}, {%4,%5,%6,%7}, {%8,%9}, {%0,%1,%2,%3};"
        : "+f"(c[0]), "+f"(c[1]), "+f"(c[2]), "+f"(c[3])
        : "r"(a[0]), "r"(a[1]), "r"(a[2]), "r"(a[3]), "r"(b[0]), "r"(b[1]));
}

// ---------------- zero scratch ----------------
__global__ void zero_scratch() {
    int i = blockIdx.x * blockDim.x + threadIdx.x;
    const int n1 = N_EVT * D / 4;   // csum float4s
    const int n2 = N_EVT / 4;       // cnt float4s
    const int n3 = N_OBJ * D / 4;   // teff float4s
    float4 z = make_float4(0.f, 0.f, 0.f, 0.f);
    if (i < n1) reinterpret_cast<float4*>(g_csum)[i] = z;
    if (i < n2) reinterpret_cast<float4*>(g_cnt)[i]  = z;
    if (i < n3) reinterpret_cast<float4*>(g_teff)[i] = z;
}

// ---------------- scale csum by 1/max(cnt,1) in place -------------------
__global__ void scale_mean() {
    int i = blockIdx.x * blockDim.x + threadIdx.x;   // N_EVT*32 float4 slots
    if (i >= N_EVT * 32) return;
    int r = i >> 5;
    float inv = 1.0f / fmaxf(__ldg(&g_cnt[r]), 1.0f);
    float4 s = reinterpret_cast<float4*>(g_csum)[i];
    reinterpret_cast<float4*>(g_csum)[i] =
        make_float4(s.x * inv, s.y * inv, s.z * inv, s.w * inv);
}

// =====================================================================
// Warp-level tf32 mma.sync GEMM with cp.async 4-stage pipeline.
// C[M,N] = act(A[M,K] @ W[N,K]^T + bias)
// CTA tile 128x128, BK=16, 128 threads = 4 warps (2m x 2n), warp 64x64.
// SMEM raw fp32, layout [row][BK+4]; cvt.rna at fragment load.
// CTX=1: A is virtual concat [A (k<128) | A2 (k>=128)], row stride 128 each.
// =====================================================================
#define BK     16
#define LDSW   20          // BK + 4 pad (words); 80B rows keep 16B alignment
#define STAGES 4
#define STG_W  (128 * LDSW)          // words per matrix per stage
#define GEMM_SMEM (STAGES * STG_W * 2 * 4)   // 81920 bytes

template<int RELU, int CTX>
__global__ __launch_bounds__(128, 2)
void gemm_mma(const float* __restrict__ A, const float* __restrict__ A2,
              const float* __restrict__ W,
              const float* __restrict__ bias, float* __restrict__ C,
              int M, int N, int K) {
    extern __shared__ uint32_t sm[];
    uint32_t* As = sm;                       // [STAGES][128*LDSW]
    uint32_t* Bs = sm + STAGES * STG_W;

    const int tid = threadIdx.x;
    const int wid = tid >> 5;
    const int lane = tid & 31;
    const int gq = lane >> 2;
    const int tg = lane & 3;
    const int warp_m = wid >> 1;
    const int warp_n = wid & 1;
    const int bm = blockIdx.y * 128;
    const int bn = blockIdx.x * 128;

    const uint32_t aAs = smem_u32(As);
    const uint32_t aBs = smem_u32(Bs);

    // loader coords: each thread copies 4 rows x 16B for A and B
    const int r0 = tid >> 2;
    const int c4 = (tid & 3) * 4;

    float acc[4][8][4];
    #pragma unroll
    for (int i = 0; i < 4; i++)
        #pragma unroll
        for (int j = 0; j < 8; j++)
            #pragma unroll
            for (int q = 0; q < 4; q++) acc[i][j][q] = 0.f;

    const int CHUNKS = K >> 4;

    auto issue = [&](int c) {
        if (c < CHUNKS) {
            const int p = c & (STAGES - 1);
            const int k0 = c * BK + c4;
            #pragma unroll
            for (int h = 0; h < 4; h++) {
                int r = r0 + h * 32;
                const float* srcA;
                if (CTX) {
                    srcA = (k0 < 128)
                         ? &A [(size_t)(bm + r) * 128 + k0]
                         : &A2[(size_t)(bm + r) * 128 + (k0 - 128)];
                } else {
                    srcA = &A[(size_t)(bm + r) * K + k0];
                }
                int szA = (bm + r < M) ? 16 : 0;
                cpasync16(aAs + (p * STG_W + r * LDSW + c4) * 4, srcA, szA);
                cpasync16(aBs + (p * STG_W + r * LDSW + c4) * 4,
                          &W[(size_t)(bn + r) * K + k0], 16);
            }
        }
        asm volatile("cp.async.commit_group;");
    };

    issue(0); issue(1); issue(2);

    for (int c = 0; c < CHUNKS; c++) {
        const int p = c & (STAGES - 1);
        asm volatile("cp.async.wait_group 2;");
        __syncthreads();
        issue(c + 3);

        const uint32_t* ap = As + p * STG_W;
        const uint32_t* bp = Bs + p * STG_W;
        #pragma unroll
        for (int ks = 0; ks < 2; ks++) {
            const int kb = ks * 8;
            uint32_t af[4][4], bf[8][2];
            #pragma unroll
            for (int mt = 0; mt < 4; mt++) {
                int row = warp_m * 64 + mt * 16 + gq;
                af[mt][0] = tf32r(__uint_as_float(ap[(row    ) * LDSW + kb + tg]));
                af[mt][1] = tf32r(__uint_as_float(ap[(row + 8) * LDSW + kb + tg]));
                af[mt][2] = tf32r(__uint_as_float(ap[(row    ) * LDSW + kb + tg + 4]));
                af[mt][3] = tf32r(__uint_as_float(ap[(row + 8) * LDSW + kb + tg + 4]));
            }
            #pragma unroll
            for (int nt = 0; nt < 8; nt++) {
                int n = warp_n * 64 + nt * 8 + gq;
                bf[nt][0] = tf32r(__uint_as_float(bp[n * LDSW + kb + tg]));
                bf[nt][1] = tf32r(__uint_as_float(bp[n * LDSW + kb + tg + 4]));
            }
            #pragma unroll
            for (int mt = 0; mt < 4; mt++)
                #pragma unroll
                for (int nt = 0; nt < 8; nt++)
                    mma_tf32(acc[mt][nt], af[mt], bf[nt]);
        }
    }

    // epilogue
    #pragma unroll
    for (int mt = 0; mt < 4; mt++) {
        #pragma unroll
        for (int half = 0; half < 2; half++) {
            int m = bm + warp_m * 64 + mt * 16 + gq + half * 8;
            if (m >= M) continue;
            #pragma unroll
            for (int nt = 0; nt < 8; nt++) {
                int n = bn + warp_n * 64 + nt * 8 + tg * 2;
                float2 bb = *reinterpret_cast<const float2*>(&bias[n]);
                float2 o;
                o.x = acc[mt][nt][half * 2 + 0] + bb.x;
                o.y = acc[mt][nt][half * 2 + 1] + bb.y;
                if (RELU) { o.x = fmaxf(o.x, 0.f); o.y = fmaxf(o.y, 0.f); }
                *reinterpret_cast<float2*>(&C[(size_t)m * N + n]) = o;
            }
        }
    }
}

// ---------------- edge scatter: h_proj[obj] -> sum into events -----------
__global__ void scatter_obj_to_evt(const int* __restrict__ obj_idx,
                                   const int* __restrict__ evt_idx) {
    int gid = blockIdx.x * blockDim.x + threadIdx.x;
    if (gid >= N_EDGE * 32) return;
    int e = gid >> 5;
    int c = gid & 31;
    int o  = __ldg(obj_idx + e);
    int ev = __ldg(evt_idx + e);
    float4 v = *reinterpret_cast<const float4*>(&g_hproj[(size_t)o * D + c * 4]);
    red4(&g_csum[(size_t)ev * D + c * 4], v);
    if (c == 0) atomicAdd(&g_cnt[ev], 1.0f);
}

// ---------------- edge scatter: h_impulse[evt] -> sum into objects -------
__global__ void scatter_evt_to_obj(const int* __restrict__ obj_idx,
                                   const int* __restrict__ evt_idx,
                                   const float* __restrict__ himp) {
    int gid = blockIdx.x * blockDim.x + threadIdx.x;
    if (gid >= N_EDGE * 32) return;
    int e = gid >> 5;
    int c = gid & 31;
    int o  = __ldg(obj_idx + e);
    int ev = __ldg(evt_idx + e);
    float4 v = *reinterpret_cast<const float4*>(&himp[(size_t)ev * D + c * 4]);
    red4(&g_teff[(size_t)o * D + c * 4], v);
}

// ---------------- GRU gate math -----------------------------------------
__global__ void gru_gates(const float* __restrict__ objX, float* __restrict__ out) {
    int gid = blockIdx.x * blockDim.x + threadIdx.x;
    if (gid >= N_OBJ * D) return;
    int r = gid >> 7;
    int d = gid & 127;
    size_t base = (size_t)r * 3 * D + d;
    float ir = g_gi[base], iz = g_gi[base + D], in_ = g_gi[base + 2 * D];
    float hr = g_gh[base], hz = g_gh[base + D], hn  = g_gh[base + 2 * D];
    float h = objX[(size_t)r * D + d];
    float rg = sigmoidf_(ir + hr);
    float z  = sigmoidf_(iz + hz);
    float n  = tanhf(in_ + rg * hn);
    out[(size_t)r * D + d] = (1.0f - z) * n + z * h;
}

// ---------------- launch ------------------------------------------------
extern "C" void kernel_launch(void* const* d_in, const int* in_sizes, int n_in,
                              void* d_out, int out_size) {
    const float* event_X  = (const float*)d_in[0];
    const float* object_X = (const float*)d_in[1];
    const int*   evt_idx  = (const int*)d_in[2];
    const int*   obj_idx  = (const int*)d_in[3];
    const float* Wa  = (const float*)d_in[4];
    const float* ba  = (const float*)d_in[5];
    const float* W1  = (const float*)d_in[6];
    const float* b1  = (const float*)d_in[7];
    const float* W2  = (const float*)d_in[8];
    const float* b2  = (const float*)d_in[9];
    const float* Wih = (const float*)d_in[10];
    const float* Whh = (const float*)d_in[11];
    const float* bih = (const float*)d_in[12];
    const float* bhh = (const float*)d_in[13];

    float* out = (float*)d_out;
    float* out_newobj = out;                       // [N_OBJ, 128]
    float* out_himp   = out + (size_t)N_OBJ * D;   // [N_EVT, 128]

    float* hproj = nullptr; cudaGetSymbolAddress((void**)&hproj, g_hproj);
    float* csum  = nullptr; cudaGetSymbolAddress((void**)&csum,  g_csum);
    float* h1    = nullptr; cudaGetSymbolAddress((void**)&h1,    g_h1);
    float* teff  = nullptr; cudaGetSymbolAddress((void**)&teff,  g_teff);
    float* gi    = nullptr; cudaGetSymbolAddress((void**)&gi,    g_gi);
    float* gh    = nullptr; cudaGetSymbolAddress((void**)&gh,    g_gh);

    static int smem_set = 0;
    if (!smem_set) {
        cudaFuncSetAttribute(gemm_mma<0, 0>,
            cudaFuncAttributeMaxDynamicSharedMemorySize, GEMM_SMEM);
        cudaFuncSetAttribute(gemm_mma<1, 1>,
            cudaFuncAttributeMaxDynamicSharedMemorySize, GEMM_SMEM);
        smem_set = 1;
    }

    // 1. zero accumulators
    {
        int n = N_EVT * D / 4;
        zero_scratch<<<(n + 255) / 256, 256>>>();
    }

    // 2. h_obj_proj = object_X @ Wa^T + ba   [N_OBJ, 128]
    gemm_mma<0, 0><<<dim3(1, (N_OBJ + 127) / 128), 128, GEMM_SMEM>>>(
        object_X, nullptr, Wa, ba, hproj, N_OBJ, D, D);

    // 3. scatter-sum object projections into events + counts
    scatter_obj_to_evt<<<(N_EDGE * 32 + 255) / 256, 256>>>(obj_idx, evt_idx);

    // 4. csum /= max(cnt,1)  (in place -> mean)
    scale_mean<<<(N_EVT * 32 + 255) / 256, 256>>>();

    // 5. h1 = relu([event_X | mean] @ W1^T + b1)   (concat fused in loader)
    gemm_mma<1, 1><<<dim3(1, (N_EVT + 127) / 128), 128, GEMM_SMEM>>>(
        event_X, csum, W1, b1, h1, N_EVT, D, 2 * D);

    // 6. h_impulse = h1 @ W2^T + b2 -> directly into output
    gemm_mma<0, 0><<<dim3(1, (N_EVT + 127) / 128), 128, GEMM_SMEM>>>(
        h1, nullptr, W2, b2, out_himp, N_EVT, D, D);

    // 7. scatter-add impulses into objects
    scatter_evt_to_obj<<<(N_EDGE * 32 + 255) / 256, 256>>>(obj_idx, evt_idx, out_himp);

    // 8. gi = total_effect @ Wih^T + bih   [N_OBJ, 384]
    gemm_mma<0, 0><<<dim3(3, (N_OBJ + 127) / 128), 128, GEMM_SMEM>>>(
        teff, nullptr, Wih, bih, gi, N_OBJ, 3 * D, D);

    // 9. gh = object_X @ Whh^T + bhh   [N_OBJ, 384]
    gemm_mma<0, 0><<<dim3(3, (N_OBJ + 127) / 128), 128, GEMM_SMEM>>>(
        object_X, nullptr, Whh, bhh, gh, N_OBJ, 3 * D, D);

    // 10. GRU gate math -> new_object_X
    gru_gates<<<(N_OBJ * D + 255) / 256, 256>>>(object_X, out_newobj);
}

// round 6
// speedup vs baseline: 2.0598x; 1.0360x over previous
#include <cuda_runtime.h>
#include <math.h>
#include <stdint.h>

#define N_OBJ  100000
#define N_EVT  200000
#define N_EDGE 1000000
#define D      128

// ---------------- scratch (device globals; no allocation) ----------------
__device__ float g_hproj[(size_t)N_OBJ * D];      // object_X @ Wa^T + ba
__device__ float g_csum [(size_t)N_EVT * D];      // scatter-sum into events
__device__ float g_cnt  [N_EVT];                  // edge counts per event
__device__ float g_h1   [(size_t)N_EVT * D];      // relu(ctx@W1^T+b1), tf32-rounded
__device__ float g_teff [(size_t)N_OBJ * D];      // scatter-add into objects
__device__ float g_gi   [(size_t)N_OBJ * 3 * D];  // x @ Wih^T + bih
__device__ float g_gh   [(size_t)N_OBJ * 3 * D];  // h @ Whh^T + bhh
__device__ float g_wrnd [163840];                 // tf32-rounded weights

// rounded-weight segment offsets
#define WR_WA   0
#define WR_W1   16384
#define WR_W2   49152
#define WR_WIH  65536
#define WR_WHH  114688

// ---------------- helpers ----------------
__device__ __forceinline__ uint32_t smem_u32(const void* p) {
    uint32_t a;
    asm("{ .reg .u64 t; cvta.to.shared.u64 t, %1; cvt.u32.u64 %0, t; }"
        : "=r"(a) : "l"(p));
    return a;
}

__device__ __forceinline__ uint32_t tf32r(float f) {
    uint32_t o;
    asm("cvt.rna.tf32.f32 %0, %1;" : "=r"(o) : "f"(f));
    return o;
}

__device__ __forceinline__ void cpasync16(uint32_t dst, const void* src, int sz) {
    asm volatile("cp.async.cg.shared.global [%0], [%1], 16, %2;"
                 :: "r"(dst), "l"(src), "r"(sz));
}

__device__ __forceinline__ void red4(float* addr, float4 v) {
    asm volatile("red.global.add.v4.f32 [%0], {%1, %2, %3, %4};"
                 :: "l"(addr), "f"(v.x), "f"(v.y), "f"(v.z), "f"(v.w)
                 : "memory");
}

__device__ __forceinline__ float sigmoidf_(float x) {
    return 1.0f / (1.0f + expf(-x));
}

__device__ __forceinline__ void mma_tf32(float* c, const uint32_t* a,
                                         const uint32_t* b) {
    asm volatile(
        "mma.sync.aligned.m16n8k8.row.col.f32.tf32.tf32.f32 "
        "{%0,%1,%2,%3}, {%4,%5,%6,%7}, {%8,%9}, {%0,%1,%2,%3};"
        : "+f"(c[0]), "+f"(c[1]), "+f"(c[2]), "+f"(c[3])
        : "r"(a[0]), "r"(a[1]), "r"(a[2]), "r"(a[3]), "r"(b[0]), "r"(b[1]));
}

// ---------------- weight pre-rounding ----------------
__global__ void round_weights(const float* __restrict__ Wa,
                              const float* __restrict__ W1,
                              const float* __restrict__ W2,
                              const float* __restrict__ Wih,
                              const float* __restrict__ Whh) {
    int i = blockIdx.x * blockDim.x + threadIdx.x;
    if (i >= 163840) return;
    float v;
    if      (i < WR_W1)  v = Wa [i - WR_WA];
    else if (i < WR_W2)  v = W1 [i - WR_W1];
    else if (i < WR_WIH) v = W2 [i - WR_W2];
    else if (i < WR_WHH) v = Wih[i - WR_WIH];
    else                 v = Whh[i - WR_WHH];
    g_wrnd[i] = __uint_as_float(tf32r(v));
}

// ---------------- zero scratch ----------------
__global__ void zero_scratch() {
    int i = blockIdx.x * blockDim.x + threadIdx.x;
    const int n1 = N_EVT * D / 4;   // csum float4s
    const int n2 = N_EVT / 4;       // cnt float4s
    const int n3 = N_OBJ * D / 4;   // teff float4s
    float4 z = make_float4(0.f, 0.f, 0.f, 0.f);
    if (i < n1) reinterpret_cast<float4*>(g_csum)[i] = z;
    if (i < n2) reinterpret_cast<float4*>(g_cnt)[i]  = z;
    if (i < n3) reinterpret_cast<float4*>(g_teff)[i] = z;
}

// =====================================================================
// Warp-level tf32 mma.sync GEMM with cp.async 4-stage pipeline.
// C[M,N] = act(A[M,K] @ W[N,K]^T + bias)
// CTA tile 128x128, BK=16, 128 threads = 4 warps (2m x 2n), warp 64x64.
// W must be pre-rounded to tf32 (no B-side cvt).
// ACVT=1: cvt.rna A fragments at load. ACVT=0: A pre-rounded, raw pass.
// CTX=1: A = virtual concat [A | csum * 1/max(cnt,1)], row stride 128 each.
// RNDOUT=1: store C tf32-rounded (for GEMM-feeding intermediates).
// =====================================================================
#define BK     16
#define LDSW   20
#define STAGES 4
#define STG_W  (128 * LDSW)
#define GEMM_SMEM (STAGES * STG_W * 2 * 4)   // 81920 bytes

template<int RELU, int CTX, int ACVT, int RNDOUT>
__global__ __launch_bounds__(128, 2)
void gemm_mma(const float* __restrict__ A, const float* __restrict__ A2,
              const float* __restrict__ W,
              const float* __restrict__ bias, float* __restrict__ C,
              int M, int N, int K) {
    extern __shared__ uint32_t sm[];
    uint32_t* As = sm;
    uint32_t* Bs = sm + STAGES * STG_W;
    __shared__ float sinv[128];

    const int tid = threadIdx.x;
    const int wid = tid >> 5;
    const int lane = tid & 31;
    const int gq = lane >> 2;
    const int tg = lane & 3;
    const int warp_m = wid >> 1;
    const int warp_n = wid & 1;
    const int bm = blockIdx.y * 128;
    const int bn = blockIdx.x * 128;

    const uint32_t aAs = smem_u32(As);
    const uint32_t aBs = smem_u32(Bs);

    const int r0 = tid >> 2;
    const int c4 = (tid & 3) * 4;

    float acc[4][8][4];
    #pragma unroll
    for (int i = 0; i < 4; i++)
        #pragma unroll
        for (int j = 0; j < 8; j++)
            #pragma unroll
            for (int q = 0; q < 4; q++) acc[i][j][q] = 0.f;

    const int CHUNKS = K >> 4;

    auto issue = [&](int c) {
        if (c < CHUNKS) {
            const int p = c & (STAGES - 1);
            const int k0 = c * BK + c4;
            #pragma unroll
            for (int h = 0; h < 4; h++) {
                int r = r0 + h * 32;
                const float* srcA;
                if (CTX) {
                    srcA = (k0 < 128)
                         ? &A [(size_t)(bm + r) * 128 + k0]
                         : &A2[(size_t)(bm + r) * 128 + (k0 - 128)];
                } else {
                    srcA = &A[(size_t)(bm + r) * K + k0];
                }
                int szA = (bm + r < M) ? 16 : 0;
                cpasync16(aAs + (p * STG_W + r * LDSW + c4) * 4, srcA, szA);
                cpasync16(aBs + (p * STG_W + r * LDSW + c4) * 4,
                          &W[(size_t)(bn + r) * K + k0], 16);
            }
        }
        asm volatile("cp.async.commit_group;");
    };

    // inv(count) table for CTX
    float invr[4][2];
    if (CTX) {
        if (tid < 128) {
            int r = bm + tid;
            float cv = (r < M) ? __ldg(&g_cnt[r]) : 1.0f;
            sinv[tid] = 1.0f / fmaxf(cv, 1.0f);
        }
    }

    issue(0); issue(1); issue(2);
    if (CTX) __syncthreads();   // sinv visible

    if (CTX) {
        #pragma unroll
        for (int mt = 0; mt < 4; mt++) {
            int row = warp_m * 64 + mt * 16 + gq;
            invr[mt][0] = sinv[row];
            invr[mt][1] = sinv[row + 8];
        }
    }

    for (int c = 0; c < CHUNKS; c++) {
        const int p = c & (STAGES - 1);
        asm volatile("cp.async.wait_group 2;");
        __syncthreads();
        issue(c + 3);

        const bool scale = CTX && (c >= 8);
        const uint32_t* ap = As + p * STG_W;
        const uint32_t* bp = Bs + p * STG_W;
        #pragma unroll
        for (int ks = 0; ks < 2; ks++) {
            const int kb = ks * 8;
            uint32_t af[4][4], bf[8][2];
            #pragma unroll
            for (int mt = 0; mt < 4; mt++) {
                int row = warp_m * 64 + mt * 16 + gq;
                uint32_t v0 = ap[(row    ) * LDSW + kb + tg];
                uint32_t v1 = ap[(row + 8) * LDSW + kb + tg];
                uint32_t v2 = ap[(row    ) * LDSW + kb + tg + 4];
                uint32_t v3 = ap[(row + 8) * LDSW + kb + tg + 4];
                if (ACVT) {
                    float f0 = __uint_as_float(v0), f1 = __uint_as_float(v1);
                    float f2 = __uint_as_float(v2), f3 = __uint_as_float(v3);
                    if (scale) {
                        f0 *= invr[mt][0]; f1 *= invr[mt][1];
                        f2 *= invr[mt][0]; f3 *= invr[mt][1];
                    }
                    af[mt][0] = tf32r(f0); af[mt][1] = tf32r(f1);
                    af[mt][2] = tf32r(f2); af[mt][3] = tf32r(f3);
                } else {
                    af[mt][0] = v0; af[mt][1] = v1;
                    af[mt][2] = v2; af[mt][3] = v3;
                }
            }
            #pragma unroll
            for (int nt = 0; nt < 8; nt++) {
                int n = warp_n * 64 + nt * 8 + gq;
                bf[nt][0] = bp[n * LDSW + kb + tg];
                bf[nt][1] = bp[n * LDSW + kb + tg + 4];
            }
            #pragma unroll
            for (int mt = 0; mt < 4; mt++)
                #pragma unroll
                for (int nt = 0; nt < 8; nt++)
                    mma_tf32(acc[mt][nt], af[mt], bf[nt]);
        }
    }

    // epilogue
    #pragma unroll
    for (int mt = 0; mt < 4; mt++) {
        #pragma unroll
        for (int half = 0; half < 2; half++) {
            int m = bm + warp_m * 64 + mt * 16 + gq + half * 8;
            if (m >= M) continue;
            #pragma unroll
            for (int nt = 0; nt < 8; nt++) {
                int n = bn + warp_n * 64 + nt * 8 + tg * 2;
                float2 bb = *reinterpret_cast<const float2*>(&bias[n]);
                float2 o;
                o.x = acc[mt][nt][half * 2 + 0] + bb.x;
                o.y = acc[mt][nt][half * 2 + 1] + bb.y;
                if (RELU) { o.x = fmaxf(o.x, 0.f); o.y = fmaxf(o.y, 0.f); }
                if (RNDOUT) {
                    o.x = __uint_as_float(tf32r(o.x));
                    o.y = __uint_as_float(tf32r(o.y));
                }
                *reinterpret_cast<float2*>(&C[(size_t)m * N + n]) = o;
            }
        }
    }
}

// ---------------- edge scatter: h_proj[obj] -> sum into events -----------
__global__ void scatter_obj_to_evt(const int* __restrict__ obj_idx,
                                   const int* __restrict__ evt_idx) {
    int gid = blockIdx.x * blockDim.x + threadIdx.x;
    if (gid >= N_EDGE * 32) return;
    int e = gid >> 5;
    int c = gid & 31;
    int o  = __ldg(obj_idx + e);
    int ev = __ldg(evt_idx + e);
    float4 v = *reinterpret_cast<const float4*>(&g_hproj[(size_t)o * D + c * 4]);
    red4(&g_csum[(size_t)ev * D + c * 4], v);
    if (c == 0) atomicAdd(&g_cnt[ev], 1.0f);
}

// ---------------- edge scatter: h_impulse[evt] -> sum into objects -------
__global__ void scatter_evt_to_obj(const int* __restrict__ obj_idx,
                                   const int* __restrict__ evt_idx,
                                   const float* __restrict__ himp) {
    int gid = blockIdx.x * blockDim.x + threadIdx.x;
    if (gid >= N_EDGE * 32) return;
    int e = gid >> 5;
    int c = gid & 31;
    int o  = __ldg(obj_idx + e);
    int ev = __ldg(evt_idx + e);
    float4 v = *reinterpret_cast<const float4*>(&himp[(size_t)ev * D + c * 4]);
    red4(&g_teff[(size_t)o * D + c * 4], v);
}

// ---------------- GRU gate math -----------------------------------------
__global__ void gru_gates(const float* __restrict__ objX, float* __restrict__ out) {
    int gid = blockIdx.x * blockDim.x + threadIdx.x;
    if (gid >= N_OBJ * D) return;
    int r = gid >> 7;
    int d = gid & 127;
    size_t base = (size_t)r * 3 * D + d;
    float ir = g_gi[base], iz = g_gi[base + D], in_ = g_gi[base + 2 * D];
    float hr = g_gh[base], hz = g_gh[base + D], hn  = g_gh[base + 2 * D];
    float h = objX[(size_t)r * D + d];
    float rg = sigmoidf_(ir + hr);
    float z  = sigmoidf_(iz + hz);
    float n  = tanhf(in_ + rg * hn);
    out[(size_t)r * D + d] = (1.0f - z) * n + z * h;
}

// ---------------- launch ------------------------------------------------
extern "C" void kernel_launch(void* const* d_in, const int* in_sizes, int n_in,
                              void* d_out, int out_size) {
    const float* event_X  = (const float*)d_in[0];
    const float* object_X = (const float*)d_in[1];
    const int*   evt_idx  = (const int*)d_in[2];
    const int*   obj_idx  = (const int*)d_in[3];
    const float* Wa  = (const float*)d_in[4];
    const float* ba  = (const float*)d_in[5];
    const float* W1  = (const float*)d_in[6];
    const float* b1  = (const float*)d_in[7];
    const float* W2  = (const float*)d_in[8];
    const float* b2  = (const float*)d_in[9];
    const float* Wih = (const float*)d_in[10];
    const float* Whh = (const float*)d_in[11];
    const float* bih = (const float*)d_in[12];
    const float* bhh = (const float*)d_in[13];

    float* out = (float*)d_out;
    float* out_newobj = out;                       // [N_OBJ, 128]
    float* out_himp   = out + (size_t)N_OBJ * D;   // [N_EVT, 128]

    float* hproj = nullptr; cudaGetSymbolAddress((void**)&hproj, g_hproj);
    float* csum  = nullptr; cudaGetSymbolAddress((void**)&csum,  g_csum);
    float* h1    = nullptr; cudaGetSymbolAddress((void**)&h1,    g_h1);
    float* teff  = nullptr; cudaGetSymbolAddress((void**)&teff,  g_teff);
    float* gi    = nullptr; cudaGetSymbolAddress((void**)&gi,    g_gi);
    float* gh    = nullptr; cudaGetSymbolAddress((void**)&gh,    g_gh);
    float* wr    = nullptr; cudaGetSymbolAddress((void**)&wr,    g_wrnd);

    static cudaStream_t sZ = nullptr, sG = nullptr;
    static cudaEvent_t eFork, eZero, eGh;
    if (!sZ) {
        cudaStreamCreateWithFlags(&sZ, cudaStreamNonBlocking);
        cudaStreamCreateWithFlags(&sG, cudaStreamNonBlocking);
        cudaEventCreateWithFlags(&eFork, cudaEventDisableTiming);
        cudaEventCreateWithFlags(&eZero, cudaEventDisableTiming);
        cudaEventCreateWithFlags(&eGh,   cudaEventDisableTiming);
        cudaFuncSetAttribute(gemm_mma<0, 0, 1, 0>,
            cudaFuncAttributeMaxDynamicSharedMemorySize, GEMM_SMEM);
        cudaFuncSetAttribute(gemm_mma<1, 1, 1, 1>,
            cudaFuncAttributeMaxDynamicSharedMemorySize, GEMM_SMEM);
        cudaFuncSetAttribute(gemm_mma<0, 0, 0, 0>,
            cudaFuncAttributeMaxDynamicSharedMemorySize, GEMM_SMEM);
    }

    // 0. round weights (main stream), then fork side streams
    round_weights<<<(163840 + 255) / 256, 256>>>(Wa, W1, W2, Wih, Whh);
    cudaEventRecord(eFork, 0);

    // side stream Z: zero accumulators (independent of weights)
    cudaStreamWaitEvent(sZ, eFork, 0);
    {
        int n = N_EVT * D / 4;
        zero_scratch<<<(n + 255) / 256, 256, 0, sZ>>>();
    }
    cudaEventRecord(eZero, sZ);

    // side stream G: gh = object_X @ Whh^T + bhh (only needs objX + weights)
    cudaStreamWaitEvent(sG, eFork, 0);
    gemm_mma<0, 0, 1, 0><<<dim3(3, (N_OBJ + 127) / 128), 128, GEMM_SMEM, sG>>>(
        object_X, nullptr, wr + WR_WHH, bhh, gh, N_OBJ, 3 * D, D);
    cudaEventRecord(eGh, sG);

    // main: h_obj_proj = object_X @ Wa^T + ba
    gemm_mma<0, 0, 1, 0><<<dim3(1, (N_OBJ + 127) / 128), 128, GEMM_SMEM>>>(
        object_X, nullptr, wr + WR_WA, ba, hproj, N_OBJ, D, D);

    // join zero, then scatter-sum into events
    cudaStreamWaitEvent(0, eZero, 0);
    scatter_obj_to_evt<<<(N_EDGE * 32 + 255) / 256, 256>>>(obj_idx, evt_idx);

    // h1 = relu([event_X | csum/cnt] @ W1^T + b1), scaling fused, output rounded
    gemm_mma<1, 1, 1, 1><<<dim3(1, (N_EVT + 127) / 128), 128, GEMM_SMEM>>>(
        event_X, csum, wr + WR_W1, b1, h1, N_EVT, D, 2 * D);

    // h_impulse = h1 @ W2^T + b2 (A pre-rounded -> no cvt at all)
    gemm_mma<0, 0, 0, 0><<<dim3(1, (N_EVT + 127) / 128), 128, GEMM_SMEM>>>(
        h1, nullptr, wr + WR_W2, b2, out_himp, N_EVT, D, D);

    // scatter-add impulses into objects
    scatter_evt_to_obj<<<(N_EDGE * 32 + 255) / 256, 256>>>(obj_idx, evt_idx, out_himp);

    // gi = total_effect @ Wih^T + bih
    gemm_mma<0, 0, 1, 0><<<dim3(3, (N_OBJ + 127) / 128), 128, GEMM_SMEM>>>(
        teff, nullptr, wr + WR_WIH, bih, gi, N_OBJ, 3 * D, D);

    // join gh, then GRU gates -> new_object_X
    cudaStreamWaitEvent(0, eGh, 0);
    gru_gates<<<(N_OBJ * D + 255) / 256, 256>>>(object_X, out_newobj);
}